// round 8
// baseline (speedup 1.0000x reference)
#include <cuda_runtime.h>
#include <math.h>
#include <stdint.h>

#define NHEADS 16
#define HDIM   128
#define SEQLEN 2048
#define NBATCH 2
#define HID    2048
#define NBH    (NBATCH*NHEADS)   // 32
#define MROWS  (NBATCH*SEQLEN)   // 4096

// Scratch for projected Q/K/V in [b,h,s,d] layout (32 MB each)
__device__ float g_Q[(size_t)NBH*SEQLEN*HDIM];
__device__ float g_K[(size_t)NBH*SEQLEN*HDIM];
__device__ float g_V[(size_t)NBH*SEQLEN*HDIM];
__device__ float2 g_rope[SEQLEN*64];   // (cos, sin) per (s, j)

__device__ __forceinline__ uint32_t f2tf32(float f) {
    uint32_t r;
    asm("cvt.rna.tf32.f32 %0, %1;" : "=r"(r) : "f"(f));
    return r;
}
__device__ __forceinline__ float tf(float f) { return __uint_as_float(f2tf32(f)); }

__device__ __forceinline__ void mma1688(float* d, const uint32_t* a, const uint32_t* b) {
    asm volatile(
        "mma.sync.aligned.m16n8k8.row.col.f32.tf32.tf32.f32 "
        "{%0,%1,%2,%3}, {%4,%5,%6,%7}, {%8,%9}, {%0,%1,%2,%3};"
        : "+f"(d[0]), "+f"(d[1]), "+f"(d[2]), "+f"(d[3])
        : "r"(a[0]), "r"(a[1]), "r"(a[2]), "r"(a[3]), "r"(b[0]), "r"(b[1]));
}

// ===========================================================================
// QKV projection via tf32 mma.sync. 128x128 CTA tile, 8 warps (2x4),
// 64x32/warp, BK=32, double-buffered. Pair-interleaved smem: within each
// 8-col k-group, cols stored (0,4,1,5,2,6,3,7) so fragment pairs (cc,cc+4)
// are one LDS.64. PAD=40 -> conflict-free fragment loads.
// ===========================================================================
#define GK_PAD    40
#define GK_BUF    (128*GK_PAD)
#define GK_SMEM_DYN (4*GK_BUF*4)        // 81920 B

__global__ __launch_bounds__(256) void qkv_mma_kernel(
    const float* __restrict__ X,
    const float* __restrict__ Wq, const float* __restrict__ bq,
    const float* __restrict__ Wk, const float* __restrict__ bk,
    const float* __restrict__ Wv, const float* __restrict__ bv)
{
    extern __shared__ float gsm[];
    float* sA = gsm;
    float* sB = gsm + 2*GK_BUF;

    const float* W; const float* bias; float* dst;
    if (blockIdx.z == 0)      { W = Wq; bias = bq; dst = g_Q; }
    else if (blockIdx.z == 1) { W = Wk; bias = bk; dst = g_K; }
    else                      { W = Wv; bias = bv; dst = g_V; }

    const int tid  = threadIdx.x;
    const int w    = tid >> 5;
    const int lane = tid & 31;
    const int g    = lane >> 2;
    const int cc   = lane & 3;
    const int wm0  = (w >> 2) * 64;
    const int wn0  = (w & 3) * 32;

    const int m0 = blockIdx.y * 128;
    const int n0 = blockIdx.x * 128;

    // staging mapping: thread owns rows lrow, lrow+64; full 8-col group lgrp
    const int lrow = tid >> 2;          // 0..63
    const int lgrp = tid & 3;           // 0..3 (BK=32 -> 4 groups)

    const float* Ap = X + (size_t)(m0 + lrow) * HID + lgrp * 8;
    const float* Bp = W + (size_t)(n0 + lrow) * HID + lgrp * 8;

    float acc[4][4][4];
    #pragma unroll
    for (int i = 0; i < 4; i++)
        #pragma unroll
        for (int j = 0; j < 4; j++)
            #pragma unroll
            for (int r = 0; r < 4; r++) acc[i][j][r] = 0.f;

    float4 palo[2], pahi[2], pblo[2], pbhi[2];

    #pragma unroll
    for (int p = 0; p < 2; p++) {
        palo[p] = *(const float4*)(Ap + (size_t)(p*64) * HID);
        pahi[p] = *(const float4*)(Ap + (size_t)(p*64) * HID + 4);
        pblo[p] = *(const float4*)(Bp + (size_t)(p*64) * HID);
        pbhi[p] = *(const float4*)(Bp + (size_t)(p*64) * HID + 4);
    }
    #pragma unroll
    for (int p = 0; p < 2; p++) {
        float* da = sA + (lrow + p*64)*GK_PAD + lgrp*8;
        float* db = sB + (lrow + p*64)*GK_PAD + lgrp*8;
        ((float2*)da)[0] = make_float2(tf(palo[p].x), tf(pahi[p].x));
        ((float2*)da)[1] = make_float2(tf(palo[p].y), tf(pahi[p].y));
        ((float2*)da)[2] = make_float2(tf(palo[p].z), tf(pahi[p].z));
        ((float2*)da)[3] = make_float2(tf(palo[p].w), tf(pahi[p].w));
        ((float2*)db)[0] = make_float2(tf(pblo[p].x), tf(pbhi[p].x));
        ((float2*)db)[1] = make_float2(tf(pblo[p].y), tf(pbhi[p].y));
        ((float2*)db)[2] = make_float2(tf(pblo[p].z), tf(pbhi[p].z));
        ((float2*)db)[3] = make_float2(tf(pblo[p].w), tf(pbhi[p].w));
    }
    __syncthreads();

    for (int c = 0; c < HID/32; c++) {
        const int cur = c & 1;

        if (c < HID/32 - 1) {
            const int k0 = (c + 1) * 32;
            #pragma unroll
            for (int p = 0; p < 2; p++) {
                palo[p] = *(const float4*)(Ap + (size_t)(p*64) * HID + k0);
                pahi[p] = *(const float4*)(Ap + (size_t)(p*64) * HID + k0 + 4);
                pblo[p] = *(const float4*)(Bp + (size_t)(p*64) * HID + k0);
                pbhi[p] = *(const float4*)(Bp + (size_t)(p*64) * HID + k0 + 4);
            }
        }

        const float* A0 = sA + cur * GK_BUF;
        const float* B0 = sB + cur * GK_BUF;
        #pragma unroll
        for (int ks = 0; ks < 4; ks++) {
            uint32_t af[4][4], bf[4][2];
            #pragma unroll
            for (int mt = 0; mt < 4; mt++) {
                const float* ap = A0 + (wm0 + mt*16 + g)*GK_PAD + ks*8 + 2*cc;
                float2 lo = *(const float2*)ap;
                float2 hi = *(const float2*)(ap + 8*GK_PAD);
                af[mt][0] = __float_as_uint(lo.x);
                af[mt][1] = __float_as_uint(hi.x);
                af[mt][2] = __float_as_uint(lo.y);
                af[mt][3] = __float_as_uint(hi.y);
            }
            #pragma unroll
            for (int nt = 0; nt < 4; nt++) {
                float2 bb = *(const float2*)(B0 + (wn0 + nt*8 + g)*GK_PAD + ks*8 + 2*cc);
                bf[nt][0] = __float_as_uint(bb.x);
                bf[nt][1] = __float_as_uint(bb.y);
            }
            #pragma unroll
            for (int mt = 0; mt < 4; mt++)
                #pragma unroll
                for (int nt = 0; nt < 4; nt++)
                    mma1688(acc[mt][nt], af[mt], bf[nt]);
        }

        if (c < HID/32 - 1) {
            float* An = sA + ((c+1) & 1) * GK_BUF;
            float* Bn = sB + ((c+1) & 1) * GK_BUF;
            #pragma unroll
            for (int p = 0; p < 2; p++) {
                float* da = An + (lrow + p*64)*GK_PAD + lgrp*8;
                float* db = Bn + (lrow + p*64)*GK_PAD + lgrp*8;
                ((float2*)da)[0] = make_float2(tf(palo[p].x), tf(pahi[p].x));
                ((float2*)da)[1] = make_float2(tf(palo[p].y), tf(pahi[p].y));
                ((float2*)da)[2] = make_float2(tf(palo[p].z), tf(pahi[p].z));
                ((float2*)da)[3] = make_float2(tf(palo[p].w), tf(pahi[p].w));
                ((float2*)db)[0] = make_float2(tf(pblo[p].x), tf(pbhi[p].x));
                ((float2*)db)[1] = make_float2(tf(pblo[p].y), tf(pbhi[p].y));
                ((float2*)db)[2] = make_float2(tf(pblo[p].z), tf(pbhi[p].z));
                ((float2*)db)[3] = make_float2(tf(pblo[p].w), tf(pbhi[p].w));
            }
        }
        __syncthreads();
    }

    #pragma unroll
    for (int mt = 0; mt < 4; mt++) {
        #pragma unroll
        for (int half = 0; half < 2; half++) {
            const int m = m0 + wm0 + mt*16 + g + half*8;
            const int b = m >> 11;
            const int s = m & (SEQLEN - 1);
            #pragma unroll
            for (int nt = 0; nt < 4; nt++) {
                const int n  = n0 + wn0 + nt*8 + cc*2;
                const int hh = n >> 7;
                const int dd = n & 127;
                float* op = dst + (((size_t)(b*NHEADS + hh))*SEQLEN + s)*HDIM + dd;
                float2 o;
                o.x = acc[mt][nt][half*2 + 0] + bias[n];
                o.y = acc[mt][nt][half*2 + 1] + bias[n + 1];
                *(float2*)op = o;
            }
        }
    }
}

// ---------------------------------------------------------------------------
// RoPE: build (cos,sin) table once (131K accurate sincosf), then apply
// memory-bound rotation to g_Q and g_K.
// ---------------------------------------------------------------------------
__global__ __launch_bounds__(256) void rope_table_kernel()
{
    int idx = blockIdx.x * 256 + threadIdx.x;   // < 2048*64
    int j = idx & 63;
    int s = idx >> 6;
    float inv = exp2f(-(float)j * 0.20762050593046112f);
    float ang = (float)s * inv;
    float sn, cs;
    sincosf(ang, &sn, &cs);
    g_rope[idx] = make_float2(cs, sn);
}

__global__ __launch_bounds__(256) void rope_apply_kernel()
{
    int idx = blockIdx.x * 256 + threadIdx.x;   // < 2*NBH*SEQLEN*64 = 2^23
    int j  = idx & 63;
    int s  = (idx >> 6) & (SEQLEN - 1);
    int t  = idx >> 17;                         // 0..63
    float* base = (t < NBH) ? g_Q : g_K;
    int bh = t & (NBH - 1);
    float* p = base + ((size_t)bh * SEQLEN + s) * HDIM;

    float2 cssn = g_rope[s*64 + j];
    float x1 = p[j], x2 = p[j + 64];
    p[j]      = x1 * cssn.x - x2 * cssn.y;
    p[j + 64] = x2 * cssn.x + x1 * cssn.y;
}

// ===========================================================================
// Flash attention via tf32 mma.sync, pair-interleaved smem everywhere.
// BM=128 (8 warps x 16 rows), BN=64, d=128.
// ===========================================================================
#define AQ_PAD 136
#define AK_PAD 136
#define AV_PAD 72
#define AP_PAD 72
#define AT_QS  (128*AQ_PAD)
#define AT_KS  (64*AK_PAD)
#define AT_VT  (128*AV_PAD)
#define AT_PS  (128*AP_PAD)
#define ATT2_SMEM ((AT_QS + AT_KS + AT_VT + AT_PS) * 4)   // 178176 B

__global__ __launch_bounds__(256, 1) void attn_mma_kernel(float* __restrict__ out)
{
    extern __shared__ float sm[];
    float* Qs = sm;                   // [128][136] interleaved d-groups
    float* Ks = Qs + AT_QS;           // [64][136]
    float* Vt = Ks + AT_KS;           // [128][72]  V^T, interleaved kv-groups
    float* Ps = Vt + AT_VT;           // [128][72]  interleaved kv-groups

    const int tid  = threadIdx.x;
    const int w    = tid >> 5;
    const int lane = tid & 31;
    const int g    = lane >> 2;
    const int cc   = lane & 3;
    const int wm   = w * 16;

    const int bh = blockIdx.y;
    const int q0 = blockIdx.x * 128;
    const float* Qg = g_Q + ((size_t)bh * SEQLEN + q0) * HDIM;
    const float* Kg = g_K + (size_t)bh * SEQLEN * HDIM;
    const float* Vg = g_V + (size_t)bh * SEQLEN * HDIM;

    // ---- stage Q: thread = (row, half); 8 groups each; interleave pairs ----
    {
        const int row  = tid >> 1;          // 0..127
        const int half = tid & 1;
        #pragma unroll
        for (int t = 0; t < 8; t++) {
            const int gr = half*8 + t;      // 0..15
            float4 lo = *(const float4*)(Qg + (size_t)row * HDIM + gr*8);
            float4 hi = *(const float4*)(Qg + (size_t)row * HDIM + gr*8 + 4);
            float* qp = Qs + row * AQ_PAD + gr*8;
            ((float2*)qp)[0] = make_float2(tf(lo.x), tf(hi.x));
            ((float2*)qp)[1] = make_float2(tf(lo.y), tf(hi.y));
            ((float2*)qp)[2] = make_float2(tf(lo.z), tf(hi.z));
            ((float2*)qp)[3] = make_float2(tf(lo.w), tf(hi.w));
        }
    }

    float o[16][4];
    #pragma unroll
    for (int i = 0; i < 16; i++)
        #pragma unroll
        for (int r = 0; r < 4; r++) o[i][r] = 0.f;
    float mi0 = -INFINITY, mi1 = -INFINITY, li0 = 0.f, li1 = 0.f;

    const float scale = 0.08838834764831844f;   // 1/sqrt(128)

    const int krow = tid >> 2;        // 0..63
    const int kgb  = (tid & 3) * 4;   // K group base (4 groups per thread)
    // permuted column for kv index krow (within its 8-group)
    const int kq   = krow & 7;
    const int pcol = (krow & ~7) + ((kq < 4) ? (2*kq) : (2*(kq-4)+1));
    // P store positions for cols 2cc, 2cc+1
    const int ppos0 = (cc < 2) ? (4*cc) : (4*cc - 7);

    __syncthreads();

    for (int n0 = 0; n0 < SEQLEN; n0 += 64) {
        // ---- stage K (interleaved d-groups) ----
        #pragma unroll
        for (int t = 0; t < 4; t++) {
            const int gr = kgb + t;     // 0..15
            float4 lo = *(const float4*)(Kg + (size_t)(n0 + krow) * HDIM + gr*8);
            float4 hi = *(const float4*)(Kg + (size_t)(n0 + krow) * HDIM + gr*8 + 4);
            float* kp = Ks + krow * AK_PAD + gr*8;
            ((float2*)kp)[0] = make_float2(tf(lo.x), tf(hi.x));
            ((float2*)kp)[1] = make_float2(tf(lo.y), tf(hi.y));
            ((float2*)kp)[2] = make_float2(tf(lo.z), tf(hi.z));
            ((float2*)kp)[3] = make_float2(tf(lo.w), tf(hi.w));
        }
        // ---- stage V^T (scatter to permuted kv column) ----
        #pragma unroll
        for (int j = 0; j < 8; j++) {
            const int kc4 = (tid & 3) + j * 4;    // 0..31 (d float4 index)
            float4 vv = *(const float4*)(Vg + (size_t)(n0 + krow) * HDIM + kc4 * 4);
            Vt[(kc4*4+0)*AV_PAD + pcol] = tf(vv.x);
            Vt[(kc4*4+1)*AV_PAD + pcol] = tf(vv.y);
            Vt[(kc4*4+2)*AV_PAD + pcol] = tf(vv.z);
            Vt[(kc4*4+3)*AV_PAD + pcol] = tf(vv.w);
        }
        __syncthreads();

        // ---- S = Q K^T (warp: 16 x 64) ----
        float s[8][4];
        #pragma unroll
        for (int nt = 0; nt < 8; nt++)
            #pragma unroll
            for (int r = 0; r < 4; r++) s[nt][r] = 0.f;

        #pragma unroll
        for (int ks = 0; ks < 16; ks++) {
            uint32_t a[4];
            const float* ap = Qs + (wm + g) * AQ_PAD + ks*8 + 2*cc;
            float2 alo = *(const float2*)ap;
            float2 ahi = *(const float2*)(ap + 8*AQ_PAD);
            a[0] = __float_as_uint(alo.x);
            a[1] = __float_as_uint(ahi.x);
            a[2] = __float_as_uint(alo.y);
            a[3] = __float_as_uint(ahi.y);
            #pragma unroll
            for (int nt = 0; nt < 8; nt++) {
                uint32_t b[2];
                float2 bb = *(const float2*)(Ks + (nt*8 + g) * AK_PAD + ks*8 + 2*cc);
                b[0] = __float_as_uint(bb.x);
                b[1] = __float_as_uint(bb.y);
                mma1688(s[nt], a, b);
            }
        }

        // ---- online softmax ----
        float rmax0 = -INFINITY, rmax1 = -INFINITY;
        #pragma unroll
        for (int nt = 0; nt < 8; nt++) {
            rmax0 = fmaxf(rmax0, fmaxf(s[nt][0], s[nt][1]));
            rmax1 = fmaxf(rmax1, fmaxf(s[nt][2], s[nt][3]));
        }
        rmax0 *= scale; rmax1 *= scale;
        rmax0 = fmaxf(rmax0, __shfl_xor_sync(0xffffffffu, rmax0, 1));
        rmax0 = fmaxf(rmax0, __shfl_xor_sync(0xffffffffu, rmax0, 2));
        rmax1 = fmaxf(rmax1, __shfl_xor_sync(0xffffffffu, rmax1, 1));
        rmax1 = fmaxf(rmax1, __shfl_xor_sync(0xffffffffu, rmax1, 2));

        const float nm0 = fmaxf(mi0, rmax0);
        const float nm1 = fmaxf(mi1, rmax1);
        const float f0 = __expf(mi0 - nm0);
        const float f1 = __expf(mi1 - nm1);
        mi0 = nm0; mi1 = nm1;

        float rs0 = 0.f, rs1 = 0.f;
        #pragma unroll
        for (int nt = 0; nt < 8; nt++) {
            float p0 = __expf(s[nt][0] * scale - nm0);
            float p1 = __expf(s[nt][1] * scale - nm0);
            float p2 = __expf(s[nt][2] * scale - nm1);
            float p3 = __expf(s[nt][3] * scale - nm1);
            rs0 += p0 + p1;
            rs1 += p2 + p3;
            float* pr0 = Ps + (wm + g)     * AP_PAD + nt*8;
            float* pr1 = Ps + (wm + g + 8) * AP_PAD + nt*8;
            pr0[ppos0]     = tf(p0);
            pr0[ppos0 + 2] = tf(p1);
            pr1[ppos0]     = tf(p2);
            pr1[ppos0 + 2] = tf(p3);
        }
        rs0 += __shfl_xor_sync(0xffffffffu, rs0, 1);
        rs0 += __shfl_xor_sync(0xffffffffu, rs0, 2);
        rs1 += __shfl_xor_sync(0xffffffffu, rs1, 1);
        rs1 += __shfl_xor_sync(0xffffffffu, rs1, 2);
        li0 = li0 * f0 + rs0;
        li1 = li1 * f1 + rs1;

        #pragma unroll
        for (int nt = 0; nt < 16; nt++) {
            o[nt][0] *= f0; o[nt][1] *= f0;
            o[nt][2] *= f1; o[nt][3] *= f1;
        }
        __syncwarp();

        // ---- O += P V^T (warp: 16 x 128) ----
        #pragma unroll
        for (int ks = 0; ks < 8; ks++) {
            uint32_t a[4];
            const float* ap = Ps + (wm + g) * AP_PAD + ks*8 + 2*cc;
            float2 alo = *(const float2*)ap;
            float2 ahi = *(const float2*)(ap + 8*AP_PAD);
            a[0] = __float_as_uint(alo.x);
            a[1] = __float_as_uint(ahi.x);
            a[2] = __float_as_uint(alo.y);
            a[3] = __float_as_uint(ahi.y);
            #pragma unroll
            for (int nt = 0; nt < 16; nt++) {
                uint32_t b[2];
                float2 bb = *(const float2*)(Vt + (nt*8 + g) * AV_PAD + ks*8 + 2*cc);
                b[0] = __float_as_uint(bb.x);
                b[1] = __float_as_uint(bb.y);
                mma1688(o[nt], a, b);
            }
        }
        __syncthreads();
    }

    // ---- epilogue ----
    const int b  = bh >> 4;
    const int hh = bh & 15;
    const float inv0 = 1.0f / li0;
    const float inv1 = 1.0f / li1;
    const int m0r = q0 + wm + g;
    #pragma unroll
    for (int nt = 0; nt < 16; nt++) {
        const int dd = nt*8 + 2*cc;
        float* op0 = out + ((size_t)(b * SEQLEN + m0r)) * HID + hh * HDIM + dd;
        float* op1 = out + ((size_t)(b * SEQLEN + m0r + 8)) * HID + hh * HDIM + dd;
        float2 r0, r1;
        r0.x = o[nt][0] * inv0; r0.y = o[nt][1] * inv0;
        r1.x = o[nt][2] * inv1; r1.y = o[nt][3] * inv1;
        *(float2*)op0 = r0;
        *(float2*)op1 = r1;
    }
}

// ---------------------------------------------------------------------------
extern "C" void kernel_launch(void* const* d_in, const int* in_sizes, int n_in,
                              void* d_out, int out_size)
{
    const float* X  = (const float*)d_in[0];
    const float* Wq = (const float*)d_in[1];
    const float* bq = (const float*)d_in[2];
    const float* Wk = (const float*)d_in[3];
    const float* bk = (const float*)d_in[4];
    const float* Wv = (const float*)d_in[5];
    const float* bv = (const float*)d_in[6];
    float* out = (float*)d_out;

    (void)cudaFuncSetAttribute(qkv_mma_kernel,
                               cudaFuncAttributeMaxDynamicSharedMemorySize,
                               GK_SMEM_DYN);
    (void)cudaFuncSetAttribute(attn_mma_kernel,
                               cudaFuncAttributeMaxDynamicSharedMemorySize,
                               ATT2_SMEM);

    dim3 gemm_grid(HID/128, MROWS/128, 3);              // 16 x 32 x 3
    qkv_mma_kernel<<<gemm_grid, 256, GK_SMEM_DYN>>>(X, Wq, bq, Wk, bk, Wv, bv);

    rope_table_kernel<<<(SEQLEN*64)/256, 256>>>();
    rope_apply_kernel<<<(2*NBH*SEQLEN*64)/256, 256>>>();

    dim3 attn_grid(SEQLEN/128, NBH);                    // 16 x 32
    attn_mma_kernel<<<attn_grid, 256, ATT2_SMEM>>>(out);
}

// round 10
// speedup vs baseline: 1.1258x; 1.1258x over previous
#include <cuda_runtime.h>
#include <math.h>
#include <stdint.h>

#define NHEADS 16
#define HDIM   128
#define SEQLEN 2048
#define NBATCH 2
#define HID    2048
#define NBH    (NBATCH*NHEADS)   // 32
#define MROWS  (NBATCH*SEQLEN)   // 4096

// Scratch for projected Q/K/V in [b,h,s,d] layout (32 MB each)
__device__ float g_Q[(size_t)NBH*SEQLEN*HDIM];
__device__ float g_K[(size_t)NBH*SEQLEN*HDIM];
__device__ float g_V[(size_t)NBH*SEQLEN*HDIM];
__device__ float2 g_rope[SEQLEN*64];   // (cos, sin) per (s, j)

__device__ __forceinline__ uint32_t f2tf32(float f) {
    uint32_t r;
    asm("cvt.rna.tf32.f32 %0, %1;" : "=r"(r) : "f"(f));
    return r;
}

__device__ __forceinline__ void mma1688(float* d, const uint32_t* a, const uint32_t* b) {
    asm volatile(
        "mma.sync.aligned.m16n8k8.row.col.f32.tf32.tf32.f32 "
        "{%0,%1,%2,%3}, {%4,%5,%6,%7}, {%8,%9}, {%0,%1,%2,%3};"
        : "+f"(d[0]), "+f"(d[1]), "+f"(d[2]), "+f"(d[3])
        : "r"(a[0]), "r"(a[1]), "r"(a[2]), "r"(a[3]), "r"(b[0]), "r"(b[1]));
}

// ===========================================================================
// QKV projection via tf32 mma.sync (round-7 passing version)
// ===========================================================================
#define GK_PAD    36
#define GK_BUF    (128*GK_PAD)
#define GK_SMEM_DYN (4*GK_BUF*4)

__global__ __launch_bounds__(256) void qkv_mma_kernel(
    const float* __restrict__ X,
    const float* __restrict__ Wq, const float* __restrict__ bq,
    const float* __restrict__ Wk, const float* __restrict__ bk,
    const float* __restrict__ Wv, const float* __restrict__ bv)
{
    extern __shared__ float gsm[];
    float* sA = gsm;
    float* sB = gsm + 2*GK_BUF;

    const float* W; const float* bias; float* dst;
    if (blockIdx.z == 0)      { W = Wq; bias = bq; dst = g_Q; }
    else if (blockIdx.z == 1) { W = Wk; bias = bk; dst = g_K; }
    else                      { W = Wv; bias = bv; dst = g_V; }

    const int tid  = threadIdx.x;
    const int w    = tid >> 5;
    const int lane = tid & 31;
    const int g    = lane >> 2;
    const int cc   = lane & 3;
    const int wm0  = (w >> 2) * 64;
    const int wn0  = (w & 3) * 32;

    const int m0 = blockIdx.y * 128;
    const int n0 = blockIdx.x * 128;

    const int lrow = tid >> 3;
    const int lc4  = tid & 7;

    const float* Ap = X + (size_t)(m0 + lrow) * HID + lc4 * 4;
    const float* Bp = W + (size_t)(n0 + lrow) * HID + lc4 * 4;

    float acc[4][4][4];
    #pragma unroll
    for (int i = 0; i < 4; i++)
        #pragma unroll
        for (int j = 0; j < 4; j++)
            #pragma unroll
            for (int r = 0; r < 4; r++) acc[i][j][r] = 0.f;

    float4 pa[4], pb[4];

    #pragma unroll
    for (int p = 0; p < 4; p++) {
        pa[p] = *(const float4*)(Ap + (size_t)(p*32) * HID);
        pb[p] = *(const float4*)(Bp + (size_t)(p*32) * HID);
    }
    #pragma unroll
    for (int p = 0; p < 4; p++) {
        uint4 ta = make_uint4(f2tf32(pa[p].x), f2tf32(pa[p].y), f2tf32(pa[p].z), f2tf32(pa[p].w));
        uint4 tb = make_uint4(f2tf32(pb[p].x), f2tf32(pb[p].y), f2tf32(pb[p].z), f2tf32(pb[p].w));
        *(uint4*)(sA + (lrow + p*32)*GK_PAD + lc4*4) = ta;
        *(uint4*)(sB + (lrow + p*32)*GK_PAD + lc4*4) = tb;
    }
    __syncthreads();

    for (int c = 0; c < HID/32; c++) {
        const int cur = c & 1;

        if (c < HID/32 - 1) {
            const int k0 = (c + 1) * 32;
            #pragma unroll
            for (int p = 0; p < 4; p++) {
                pa[p] = *(const float4*)(Ap + (size_t)(p*32) * HID + k0);
                pb[p] = *(const float4*)(Bp + (size_t)(p*32) * HID + k0);
            }
        }

        const float* A0 = sA + cur * GK_BUF;
        const float* B0 = sB + cur * GK_BUF;
        #pragma unroll
        for (int ks = 0; ks < 32; ks += 8) {
            uint32_t af[4][4], bf[4][2];
            #pragma unroll
            for (int mt = 0; mt < 4; mt++) {
                const float* ap = A0 + (wm0 + mt*16 + g)*GK_PAD + ks + cc;
                af[mt][0] = __float_as_uint(ap[0]);
                af[mt][1] = __float_as_uint(ap[8*GK_PAD]);
                af[mt][2] = __float_as_uint(ap[4]);
                af[mt][3] = __float_as_uint(ap[8*GK_PAD + 4]);
            }
            #pragma unroll
            for (int nt = 0; nt < 4; nt++) {
                const float* bp = B0 + (wn0 + nt*8 + g)*GK_PAD + ks + cc;
                bf[nt][0] = __float_as_uint(bp[0]);
                bf[nt][1] = __float_as_uint(bp[4]);
            }
            #pragma unroll
            for (int mt = 0; mt < 4; mt++)
                #pragma unroll
                for (int nt = 0; nt < 4; nt++)
                    mma1688(acc[mt][nt], af[mt], bf[nt]);
        }

        if (c < HID/32 - 1) {
            float* An = sA + ((c+1) & 1) * GK_BUF;
            float* Bn = sB + ((c+1) & 1) * GK_BUF;
            #pragma unroll
            for (int p = 0; p < 4; p++) {
                uint4 ta = make_uint4(f2tf32(pa[p].x), f2tf32(pa[p].y), f2tf32(pa[p].z), f2tf32(pa[p].w));
                uint4 tb = make_uint4(f2tf32(pb[p].x), f2tf32(pb[p].y), f2tf32(pb[p].z), f2tf32(pb[p].w));
                *(uint4*)(An + (lrow + p*32)*GK_PAD + lc4*4) = ta;
                *(uint4*)(Bn + (lrow + p*32)*GK_PAD + lc4*4) = tb;
            }
        }
        __syncthreads();
    }

    #pragma unroll
    for (int mt = 0; mt < 4; mt++) {
        #pragma unroll
        for (int half = 0; half < 2; half++) {
            const int m = m0 + wm0 + mt*16 + g + half*8;
            const int b = m >> 11;
            const int s = m & (SEQLEN - 1);
            #pragma unroll
            for (int nt = 0; nt < 4; nt++) {
                const int n  = n0 + wn0 + nt*8 + cc*2;
                const int hh = n >> 7;
                const int dd = n & 127;
                float* op = dst + (((size_t)(b*NHEADS + hh))*SEQLEN + s)*HDIM + dd;
                float2 o;
                o.x = acc[mt][nt][half*2 + 0] + bias[n];
                o.y = acc[mt][nt][half*2 + 1] + bias[n + 1];
                *(float2*)op = o;
            }
        }
    }
}

// ---------------------------------------------------------------------------
// RoPE: build (cos,sin) table once (131K accurate sincosf), then apply
// memory-bound rotation to g_Q and g_K.
// ---------------------------------------------------------------------------
__global__ __launch_bounds__(256) void rope_table_kernel()
{
    int idx = blockIdx.x * 256 + threadIdx.x;   // < 2048*64
    int j = idx & 63;
    int s = idx >> 6;
    float inv = exp2f(-(float)j * 0.20762050593046112f);
    float ang = (float)s * inv;
    float sn, cs;
    sincosf(ang, &sn, &cs);
    g_rope[idx] = make_float2(cs, sn);
}

__global__ __launch_bounds__(256) void rope_apply_kernel()
{
    int idx = blockIdx.x * 256 + threadIdx.x;   // < 2*NBH*SEQLEN*64 = 2^23
    int j  = idx & 63;
    int s  = (idx >> 6) & (SEQLEN - 1);
    int t  = idx >> 17;                         // 0..63
    float* base = (t < NBH) ? g_Q : g_K;
    int bh = t & (NBH - 1);
    float* p = base + ((size_t)bh * SEQLEN + s) * HDIM;

    float2 cssn = g_rope[s*64 + j];
    float x1 = p[j], x2 = p[j + 64];
    p[j]      = x1 * cssn.x - x2 * cssn.y;
    p[j + 64] = x2 * cssn.x + x1 * cssn.y;
}

// ===========================================================================
// Flash attention via tf32 mma.sync (round-7 passing version).
// BM=128 queries/CTA (8 warps x 16 rows), BN=64 kv/tile, d=128.
// ===========================================================================
#define AQ_PAD 132
#define AK_PAD 132
#define AV_PAD 68
#define AP_PAD 68
#define AT_QS  (128*AQ_PAD)
#define AT_KS  (64*AK_PAD)
#define AT_VT  (128*AV_PAD)
#define AT_PS  (128*AP_PAD)
#define ATT2_SMEM ((AT_QS + AT_KS + AT_VT + AT_PS) * 4)   // 171008 B

__global__ __launch_bounds__(256, 1) void attn_mma_kernel(float* __restrict__ out)
{
    extern __shared__ float sm[];
    float* Qs = sm;                   // [128][132] tf32
    float* Ks = Qs + AT_QS;           // [64][132]  tf32
    float* Vt = Ks + AT_KS;           // [128][68]  tf32 (V transposed: [d][kv])
    float* Ps = Vt + AT_VT;           // [128][68]  tf32

    const int tid  = threadIdx.x;
    const int w    = tid >> 5;
    const int lane = tid & 31;
    const int g    = lane >> 2;       // 0..7
    const int cc   = lane & 3;        // 0..3
    const int wm   = w * 16;          // warp's query-row base in tile

    const int bh = blockIdx.y;
    const int q0 = blockIdx.x * 128;
    const float* Qg = g_Q + ((size_t)bh * SEQLEN + q0) * HDIM;
    const float* Kg = g_K + (size_t)bh * SEQLEN * HDIM;
    const float* Vg = g_V + (size_t)bh * SEQLEN * HDIM;

    // ---- stage Q (tf32) ----
    {
        const int row  = tid >> 1;          // 0..127
        const int half = tid & 1;
        #pragma unroll
        for (int j = 0; j < 16; j++) {
            const int c4 = half * 16 + j;   // 0..31
            float4 v = *(const float4*)(Qg + (size_t)row * HDIM + c4 * 4);
            uint4 t = make_uint4(f2tf32(v.x), f2tf32(v.y), f2tf32(v.z), f2tf32(v.w));
            *(uint4*)(Qs + row * AQ_PAD + c4 * 4) = t;
        }
    }

    float o[16][4];
    #pragma unroll
    for (int i = 0; i < 16; i++)
        #pragma unroll
        for (int r = 0; r < 4; r++) o[i][r] = 0.f;
    float mi0 = -INFINITY, mi1 = -INFINITY, li0 = 0.f, li1 = 0.f;

    const float scale = 0.08838834764831844f;   // 1/sqrt(128)

    const int krow = tid >> 2;        // 0..63
    const int kq4  = tid & 3;

    __syncthreads();

    for (int n0 = 0; n0 < SEQLEN; n0 += 64) {
        // ---- stage K (tf32) and V^T (tf32) ----
        #pragma unroll
        for (int j = 0; j < 8; j++) {
            const int c4 = kq4 * 8 + j;     // 0..31
            float4 v = *(const float4*)(Kg + (size_t)(n0 + krow) * HDIM + c4 * 4);
            uint4 t = make_uint4(f2tf32(v.x), f2tf32(v.y), f2tf32(v.z), f2tf32(v.w));
            *(uint4*)(Ks + krow * AK_PAD + c4 * 4) = t;

            const int kc4 = kq4 + j * 4;    // 0..31
            float4 vv = *(const float4*)(Vg + (size_t)(n0 + krow) * HDIM + kc4 * 4);
            Vt[(kc4*4+0)*AV_PAD + krow] = __uint_as_float(f2tf32(vv.x));
            Vt[(kc4*4+1)*AV_PAD + krow] = __uint_as_float(f2tf32(vv.y));
            Vt[(kc4*4+2)*AV_PAD + krow] = __uint_as_float(f2tf32(vv.z));
            Vt[(kc4*4+3)*AV_PAD + krow] = __uint_as_float(f2tf32(vv.w));
        }
        __syncthreads();

        // ---- S = Q K^T (warp: 16 x 64) ----
        float s[8][4];
        #pragma unroll
        for (int nt = 0; nt < 8; nt++)
            #pragma unroll
            for (int r = 0; r < 4; r++) s[nt][r] = 0.f;

        #pragma unroll
        for (int ks = 0; ks < 16; ks++) {
            uint32_t a[4];
            const float* ap = Qs + (wm + g) * AQ_PAD + ks * 8 + cc;
            a[0] = __float_as_uint(ap[0]);
            a[1] = __float_as_uint(ap[8*AQ_PAD]);
            a[2] = __float_as_uint(ap[4]);
            a[3] = __float_as_uint(ap[8*AQ_PAD + 4]);
            #pragma unroll
            for (int nt = 0; nt < 8; nt++) {
                uint32_t b[2];
                const float* bp = Ks + (nt*8 + g) * AK_PAD + ks * 8 + cc;
                b[0] = __float_as_uint(bp[0]);
                b[1] = __float_as_uint(bp[4]);
                mma1688(s[nt], a, b);
            }
        }

        // ---- online softmax (rows g and g+8 of warp tile) ----
        float rmax0 = -INFINITY, rmax1 = -INFINITY;
        #pragma unroll
        for (int nt = 0; nt < 8; nt++) {
            rmax0 = fmaxf(rmax0, fmaxf(s[nt][0], s[nt][1]));
            rmax1 = fmaxf(rmax1, fmaxf(s[nt][2], s[nt][3]));
        }
        rmax0 *= scale; rmax1 *= scale;
        rmax0 = fmaxf(rmax0, __shfl_xor_sync(0xffffffffu, rmax0, 1));
        rmax0 = fmaxf(rmax0, __shfl_xor_sync(0xffffffffu, rmax0, 2));
        rmax1 = fmaxf(rmax1, __shfl_xor_sync(0xffffffffu, rmax1, 1));
        rmax1 = fmaxf(rmax1, __shfl_xor_sync(0xffffffffu, rmax1, 2));

        const float nm0 = fmaxf(mi0, rmax0);
        const float nm1 = fmaxf(mi1, rmax1);
        const float f0 = __expf(mi0 - nm0);
        const float f1 = __expf(mi1 - nm1);
        mi0 = nm0; mi1 = nm1;

        float rs0 = 0.f, rs1 = 0.f;
        #pragma unroll
        for (int nt = 0; nt < 8; nt++) {
            float p0 = __expf(s[nt][0] * scale - nm0);
            float p1 = __expf(s[nt][1] * scale - nm0);
            float p2 = __expf(s[nt][2] * scale - nm1);
            float p3 = __expf(s[nt][3] * scale - nm1);
            rs0 += p0 + p1;
            rs1 += p2 + p3;
            float2 w0, w1;
            w0.x = __uint_as_float(f2tf32(p0));
            w0.y = __uint_as_float(f2tf32(p1));
            w1.x = __uint_as_float(f2tf32(p2));
            w1.y = __uint_as_float(f2tf32(p3));
            *(float2*)(Ps + (wm + g)     * AP_PAD + nt*8 + 2*cc) = w0;
            *(float2*)(Ps + (wm + g + 8) * AP_PAD + nt*8 + 2*cc) = w1;
        }
        rs0 += __shfl_xor_sync(0xffffffffu, rs0, 1);
        rs0 += __shfl_xor_sync(0xffffffffu, rs0, 2);
        rs1 += __shfl_xor_sync(0xffffffffu, rs1, 1);
        rs1 += __shfl_xor_sync(0xffffffffu, rs1, 2);
        li0 = li0 * f0 + rs0;
        li1 = li1 * f1 + rs1;

        #pragma unroll
        for (int nt = 0; nt < 16; nt++) {
            o[nt][0] *= f0; o[nt][1] *= f0;
            o[nt][2] *= f1; o[nt][3] *= f1;
        }
        __syncwarp();

        // ---- O += P V^T (warp: 16 x 128) ----
        #pragma unroll
        for (int ks = 0; ks < 8; ks++) {
            uint32_t a[4];
            const float* ap = Ps + (wm + g) * AP_PAD + ks * 8 + cc;
            a[0] = __float_as_uint(ap[0]);
            a[1] = __float_as_uint(ap[8*AP_PAD]);
            a[2] = __float_as_uint(ap[4]);
            a[3] = __float_as_uint(ap[8*AP_PAD + 4]);
            #pragma unroll
            for (int nt = 0; nt < 16; nt++) {
                uint32_t b[2];
                const float* bp = Vt + (nt*8 + g) * AV_PAD + ks * 8 + cc;
                b[0] = __float_as_uint(bp[0]);
                b[1] = __float_as_uint(bp[4]);
                mma1688(o[nt], a, b);
            }
        }
        __syncthreads();
    }

    // ---- epilogue: out[b, s, hh*128 + d] = o / l ----
    const int b  = bh >> 4;
    const int hh = bh & 15;
    const float inv0 = 1.0f / li0;
    const float inv1 = 1.0f / li1;
    const int m0r = q0 + wm + g;
    #pragma unroll
    for (int nt = 0; nt < 16; nt++) {
        const int dd = nt*8 + 2*cc;
        float* op0 = out + ((size_t)(b * SEQLEN + m0r)) * HID + hh * HDIM + dd;
        float* op1 = out + ((size_t)(b * SEQLEN + m0r + 8)) * HID + hh * HDIM + dd;
        float2 r0, r1;
        r0.x = o[nt][0] * inv0; r0.y = o[nt][1] * inv0;
        r1.x = o[nt][2] * inv1; r1.y = o[nt][3] * inv1;
        *(float2*)op0 = r0;
        *(float2*)op1 = r1;
    }
}

// ---------------------------------------------------------------------------
extern "C" void kernel_launch(void* const* d_in, const int* in_sizes, int n_in,
                              void* d_out, int out_size)
{
    const float* X  = (const float*)d_in[0];
    const float* Wq = (const float*)d_in[1];
    const float* bq = (const float*)d_in[2];
    const float* Wk = (const float*)d_in[3];
    const float* bk = (const float*)d_in[4];
    const float* Wv = (const float*)d_in[5];
    const float* bv = (const float*)d_in[6];
    float* out = (float*)d_out;

    (void)cudaFuncSetAttribute(qkv_mma_kernel,
                               cudaFuncAttributeMaxDynamicSharedMemorySize,
                               GK_SMEM_DYN);
    (void)cudaFuncSetAttribute(attn_mma_kernel,
                               cudaFuncAttributeMaxDynamicSharedMemorySize,
                               ATT2_SMEM);

    dim3 gemm_grid(HID/128, MROWS/128, 3);              // 16 x 32 x 3
    qkv_mma_kernel<<<gemm_grid, 256, GK_SMEM_DYN>>>(X, Wq, bq, Wk, bk, Wv, bv);

    rope_table_kernel<<<(SEQLEN*64)/256, 256>>>();
    rope_apply_kernel<<<(2*NBH*SEQLEN*64)/256, 256>>>();

    dim3 attn_grid(SEQLEN/128, NBH);                    // 16 x 32
    attn_mma_kernel<<<attn_grid, 256, ATT2_SMEM>>>(out);
}